// round 15
// baseline (speedup 1.0000x reference)
#include <cuda_runtime.h>
#include <math.h>

#define B_ 2
#define T_ 8192
#define H_ 8
#define D_ 64
#define NC_ 128
#define M_ 4
#define W_ 64
#define BH_ (B_*H_)
#define TT_ (2*T_)
#define OUT_ELEMS ((size_t)B_*H_*T_*D_)

__device__ float              g_score[(size_t)BH_*2*NC_*T_];   // 128 MB
__device__ int                g_qidx[BH_*NC_*W_];
__device__ int                g_kidx[BH_*NC_*W_];
__device__ int                g_cnt[BH_*T_];
__device__ double             g_aux;

// ---- f32x2 helpers (sm_100+) ---- (attn only; dist numerics frozen scalar)
__device__ __forceinline__ unsigned long long pack2(float lo, float hi) {
    unsigned long long r;
    asm("mov.b64 %0, {%1,%2};" : "=l"(r) : "f"(lo), "f"(hi));
    return r;
}
__device__ __forceinline__ unsigned long long fma2(unsigned long long a, unsigned long long b, unsigned long long c) {
    unsigned long long d;
    asm("fma.rn.f32x2 %0, %1, %2, %3;" : "=l"(d) : "l"(a), "l"(b), "l"(c));
    return d;
}
__device__ __forceinline__ void unpack2(unsigned long long v, float& lo, float& hi) {
    asm("mov.b64 {%0,%1}, %2;" : "=f"(lo), "=f"(hi) : "l"(v));
}

// ---------------------------------------------------------------------------
// Kernel 0: zero output (atomic target), counts, aux  (R10 serial form)
// ---------------------------------------------------------------------------
__global__ __launch_bounds__(256) void zero_kernel(float* __restrict__ out) {
    size_t i = (size_t)blockIdx.x * 256 + threadIdx.x;
    if (i < OUT_ELEMS / 4) reinterpret_cast<float4*>(out)[i] = make_float4(0.f, 0.f, 0.f, 0.f);
    if (i < (size_t)BH_ * T_) g_cnt[i] = 0;
    if (i == 0) g_aux = 0.0;
}

// ---------------------------------------------------------------------------
// Kernel 1 — FROZEN R2 scalar arithmetic, R10-proven unroll 2. DO NOT TOUCH.
// ---------------------------------------------------------------------------
__global__ __launch_bounds__(256) void dist_kernel(const float* __restrict__ q,
                                                   const float* __restrict__ k,
                                                   const float* __restrict__ means) {
    __shared__ float sm[NC_ * D_];
    __shared__ float sm2[NC_];
    __shared__ float sred[256];
    const int tid = threadIdx.x;
    const int bh  = blockIdx.y;
    const int h   = bh & (H_ - 1);

    const float* mp = means + (size_t)h * NC_ * D_;
    for (int i = tid; i < NC_ * D_; i += 256) sm[i] = mp[i];
    __syncthreads();
    if (tid < NC_) {
        float s = 0.f;
        #pragma unroll
        for (int d = 0; d < D_; d++) { float m = sm[tid * D_ + d]; s += m * m; }
        sm2[tid] = s;
    }
    __syncthreads();

    const int tt   = blockIdx.x * 256 + tid;          // 0 .. 16383
    const int side = (tt >= T_) ? 1 : 0;
    const int tok  = tt - side * T_;
    const float* src = (side ? k : q) + ((size_t)bh * T_ + tok) * D_;

    float x[D_];
    float x2r = 0.f;
    #pragma unroll
    for (int i = 0; i < 16; i++) {
        float4 v = *reinterpret_cast<const float4*>(src + i * 4);
        x[i*4+0] = v.x; x[i*4+1] = v.y; x[i*4+2] = v.z; x[i*4+3] = v.w;
        x2r += v.x*v.x + v.y*v.y + v.z*v.z + v.w*v.w;
    }
    const float s = 1.f / (__fsqrt_rn(x2r) + 1e-6f);
    #pragma unroll
    for (int i = 0; i < D_; i++) x[i] *= s;
    float x2 = 0.f;
    #pragma unroll
    for (int i = 0; i < D_; i++) x2 += x[i] * x[i];

    float* srow = g_score + ((size_t)(bh * 2 + side) * NC_) * T_ + tok;
    float mind2 = 3.402823466e38f;
    #pragma unroll 2
    for (int c = 0; c < NC_; c++) {
        const float4* mr = reinterpret_cast<const float4*>(sm + c * D_);
        float dot = 0.f;
        #pragma unroll
        for (int i = 0; i < 16; i++) {
            float4 m4 = mr[i];
            dot += x[i*4+0]*m4.x + x[i*4+1]*m4.y + x[i*4+2]*m4.z + x[i*4+3]*m4.w;
        }
        float d2 = fmaxf((x2 + sm2[c]) - 2.f * dot, 0.f);
        srow[(size_t)c * T_] = d2;
        mind2 = fminf(mind2, d2);
    }

    sred[tid] = mind2;
    __syncthreads();
    for (int o = 128; o > 0; o >>= 1) {
        if (tid < o) sred[tid] += sred[tid + o];
        __syncthreads();
    }
    if (tid == 0) atomicAdd(&g_aux, (double)sred[0]);
}

// ---------------------------------------------------------------------------
// Kernel 2: exact top-64 — same 2-way bisection + window refinement logic as
// R9/R10, rebalanced to 512 threads x 16 elements (R14 ncu: 80 regs, occ 36%,
// ALU-bound). Thread->token map tid + j*512; selection set identical
// (order-insensitive downstream).
// ---------------------------------------------------------------------------
__global__ __launch_bounds__(512) void select_kernel() {
    __shared__ unsigned long long cand[2048];
    __shared__ int selIdx[64];
    __shared__ int s_wcnt[16];
    __shared__ unsigned s_wmn[16], s_wmx[16];
    __shared__ unsigned s_lo, s_hi;
    __shared__ int s_nsel, s_ncand;
    __shared__ unsigned long long s_wmin[16], s_min;

    const int tid  = threadIdx.x;
    const int lane = tid & 31, wid = tid >> 5;
    const int c    = blockIdx.x & (NC_ - 1);
    const int side = (blockIdx.x >> 7) & 1;
    const int bh   = blockIdx.x >> 8;
    const float* sc = g_score + ((size_t)((bh * 2 + side) * NC_ + c)) * T_;

    if (tid == 0) { s_nsel = 0; s_ncand = 0; }

    // ---- load 16 elements into registers (order-preserving bit map) ----
    unsigned ord[16];
    unsigned mn = 0xFFFFFFFFu, mx = 0u;
    #pragma unroll
    for (int j = 0; j < 16; j++) {
        unsigned u = __float_as_uint(sc[tid + j * 512]) | 0x80000000u;  // d2>=0
        ord[j] = u;
        mn = min(mn, u); mx = max(mx, u);
    }
    #pragma unroll
    for (int o = 16; o; o >>= 1) {
        mn = min(mn, __shfl_xor_sync(0xFFFFFFFFu, mn, o));
        mx = max(mx, __shfl_xor_sync(0xFFFFFFFFu, mx, o));
    }
    if (lane == 0) { s_wmn[wid] = mn; s_wmx[wid] = mx; }
    __syncthreads();
    if (tid == 0) {
        unsigned glo = s_wmn[0], ghi = s_wmx[0];
        for (int w2 = 1; w2 < 16; w2++) { glo = min(glo, s_wmn[w2]); ghi = max(ghi, s_wmx[w2]); }
        s_lo = glo; s_hi = ghi;
    }
    __syncthreads();

    // ---- 2-way bisection: smallest p with count(ord <= p) >= 64 ----
    while (true) {
        unsigned lo = s_lo, hi = s_hi;
        if (lo >= hi) break;
        unsigned mid = lo + ((hi - lo) >> 1);
        int cnt = 0;
        #pragma unroll
        for (int j = 0; j < 16; j++) cnt += (ord[j] <= mid) ? 1 : 0;
        #pragma unroll
        for (int o = 16; o; o >>= 1) cnt += __shfl_xor_sync(0xFFFFFFFFu, cnt, o);
        if (lane == 0) s_wcnt[wid] = cnt;
        __syncthreads();
        if (tid == 0) {
            int t = 0;
            for (int w2 = 0; w2 < 16; w2++) t += s_wcnt[w2];
            if (t >= W_) s_hi = mid; else s_lo = mid + 1;
        }
        __syncthreads();
    }
    const unsigned V64 = s_lo;
    const unsigned lowcut  = (V64 >= 0x80000010u) ? (V64 - 16u) : 0x80000000u;
    const unsigned highcut = (V64 <= 0xFFFFFFEFu) ? (V64 + 16u) : 0xFFFFFFFFu;

    // ---- classify (token index = tid + j*512) ----
    #pragma unroll
    for (int j = 0; j < 16; j++) {
        unsigned u = ord[j];
        if (u < lowcut) {
            selIdx[atomicAdd(&s_nsel, 1)] = tid + j * 512;
        } else if (u <= highcut) {
            int p = atomicAdd(&s_ncand, 1);
            if (p < 2048) {
                float d2v = __uint_as_float(u & 0x7FFFFFFFu);
                unsigned sq = __float_as_uint(__fsqrt_rn(d2v));
                cand[p] = ((unsigned long long)sq << 32) | (unsigned)(tid + j * 512);
            }
        }
    }
    __syncthreads();

    const int nbelow = s_nsel;
    const int r = W_ - nbelow;
    const int ncand = min(s_ncand, 2048);
    for (int it = 0; it < r; it++) {
        unsigned long long mv = 0xFFFFFFFFFFFFFFFFull;
        for (int p = tid; p < ncand; p += 512) {
            unsigned long long cv = cand[p];
            if (cv < mv) mv = cv;
        }
        #pragma unroll
        for (int o = 16; o; o >>= 1) {
            unsigned long long ov = __shfl_down_sync(0xFFFFFFFFu, mv, o);
            if (ov < mv) mv = ov;
        }
        if (lane == 0) s_wmin[wid] = mv;
        __syncthreads();
        if (tid == 0) {
            unsigned long long m = s_wmin[0];
            for (int w2 = 1; w2 < 16; w2++) if (s_wmin[w2] < m) m = s_wmin[w2];
            s_min = m;
            selIdx[nbelow + it] = (int)(m & 0xFFFFFFFFull);
        }
        __syncthreads();
        unsigned long long m = s_min;
        for (int p = tid; p < ncand; p += 512)
            if (cand[p] == m) cand[p] = 0xFFFFFFFFFFFFFFFFull;
        __syncthreads();
    }

    int* dst = (side == 0 ? g_qidx : g_kidx) + (bh * NC_ + c) * W_;
    if (tid < W_) {
        int idx = selIdx[tid];
        dst[tid] = idx;
        if (side == 0) atomicAdd(&g_cnt[bh * T_ + idx], 1);
    }
}

// ---------------------------------------------------------------------------
// Kernel 3 (UNCHANGED from R10): attention with phase-overlaid smem (36KB).
// ---------------------------------------------------------------------------
#define A_OFF    0
#define B_OFF    4352
#define INT_OFF  (4352 + 4624)
#define ATTN_SMEM ((INT_OFF + 192) * 4)

__global__ __launch_bounds__(256) void attn_kernel(const float* __restrict__ q,
                                                   const float* __restrict__ k,
                                                   const float* __restrict__ v,
                                                   const float* __restrict__ mk,
                                                   const float* __restrict__ mv,
                                                   float* __restrict__ out) {
    extern __shared__ float sf[];
    float* ks_t = sf + A_OFF;     // [d][j] pitch 68   (QK phase)
    float* vs   = sf + A_OFF;     // [j][dd] pitch 64  (AV phase)
    float* qs_t = sf + B_OFF;     // [d][row] pitch 68 (QK phase)
    float* dt   = sf + B_OFF;     // [j][i]  pitch 68  (AV phase)
    int*   qi   = (int*)(sf + INT_OFF);
    int*   ki   = qi + 64;
    float* sinv = (float*)(ki + 64);

    const int tid = threadIdx.x;
    const int c   = blockIdx.x & (NC_ - 1);
    const int bh  = blockIdx.x >> 7;
    const int h   = bh & (H_ - 1);

    if (tid < 64) {
        int qv = g_qidx[(bh * NC_ + c) * W_ + tid];
        qi[tid] = qv;
        ki[tid] = g_kidx[(bh * NC_ + c) * W_ + tid];
        sinv[tid] = 1.0f / ((float)g_cnt[bh * T_ + qv] + 1e-5f);
    }
    __syncthreads();

    // ---- gather q -> qs_t (transposed) ----
    {
        int row = tid >> 2, cg = tid & 3;
        const float* src = q + ((size_t)bh * T_ + qi[row]) * D_ + cg * 16;
        #pragma unroll
        for (int u = 0; u < 4; u++) {
            float4 t4 = *reinterpret_cast<const float4*>(src + u * 4);
            int d0 = cg * 16 + u * 4;
            qs_t[(d0+0)*68 + row] = t4.x;
            qs_t[(d0+1)*68 + row] = t4.y;
            qs_t[(d0+2)*68 + row] = t4.z;
            qs_t[(d0+3)*68 + row] = t4.w;
        }
    }
    // ---- gather kf -> ks_t (transposed); rows 0..3 = memory keys ----
    {
        int cg = tid & 3;
        for (int row = tid >> 2; row < 68; row += 64) {
            const float* sk = (row < 4)
                ? mk + ((size_t)(h * NC_ + c) * M_ + row) * D_
                : k  + ((size_t)bh * T_ + ki[row - 4]) * D_;
            #pragma unroll
            for (int u = 0; u < 4; u++) {
                int d0 = cg * 16 + u * 4;
                float4 a = *reinterpret_cast<const float4*>(sk + d0);
                ks_t[(d0+0)*68 + row] = a.x;
                ks_t[(d0+1)*68 + row] = a.y;
                ks_t[(d0+2)*68 + row] = a.z;
                ks_t[(d0+3)*68 + row] = a.w;
            }
        }
    }
    __syncthreads();

    const int tx = tid & 15, ty = tid >> 4;
    const int r0 = 4 * ty, c0 = 4 * tx;

    // ---- QK^T main tile -> registers w[r][c] ----
    float w[4][4];
    {
        unsigned long long a00=0, a01=0, a10=0, a11=0, a20=0, a21=0, a30=0, a31=0;
        #pragma unroll 8
        for (int d = 0; d < D_; d++) {
            float4 q4 = *reinterpret_cast<const float4*>(&qs_t[d * 68 + r0]);
            ulonglong2 k2 = *reinterpret_cast<const ulonglong2*>(&ks_t[d * 68 + c0]);
            unsigned long long p0 = pack2(q4.x, q4.x);
            unsigned long long p1 = pack2(q4.y, q4.y);
            unsigned long long p2 = pack2(q4.z, q4.z);
            unsigned long long p3 = pack2(q4.w, q4.w);
            a00 = fma2(p0, k2.x, a00); a01 = fma2(p0, k2.y, a01);
            a10 = fma2(p1, k2.x, a10); a11 = fma2(p1, k2.y, a11);
            a20 = fma2(p2, k2.x, a20); a21 = fma2(p2, k2.y, a21);
            a30 = fma2(p3, k2.x, a30); a31 = fma2(p3, k2.y, a31);
        }
        unpack2(a00, w[0][0], w[0][1]); unpack2(a01, w[0][2], w[0][3]);
        unpack2(a10, w[1][0], w[1][1]); unpack2(a11, w[1][2], w[1][3]);
        unpack2(a20, w[2][0], w[2][1]); unpack2(a21, w[2][2], w[2][3]);
        unpack2(a30, w[3][0], w[3][1]); unpack2(a31, w[3][2], w[3][3]);
        #pragma unroll
        for (int r = 0; r < 4; r++)
            #pragma unroll
            for (int cc = 0; cc < 4; cc++) w[r][cc] *= 0.125f;
    }

    // ---- extra cols 64..67 (memory keys): lanes tx<4 ----
    float ex[4] = {0.f, 0.f, 0.f, 0.f};
    const bool hasex = (tx < 4);
    if (hasex) {
        const int jm = 64 + tx;
        #pragma unroll 8
        for (int d = 0; d < D_; d++) {
            float4 q4 = *reinterpret_cast<const float4*>(&qs_t[d * 68 + r0]);
            float kv = ks_t[d * 68 + jm];
            ex[0] += q4.x * kv; ex[1] += q4.y * kv;
            ex[2] += q4.z * kv; ex[3] += q4.w * kv;
        }
        #pragma unroll
        for (int r = 0; r < 4; r++) ex[r] *= 0.125f;
    }

    // ---- row softmax in registers (rows owned by 16 tx lanes) ----
    #pragma unroll
    for (int r = 0; r < 4; r++) {
        float m = fmaxf(fmaxf(w[r][0], w[r][1]), fmaxf(w[r][2], w[r][3]));
        if (hasex) m = fmaxf(m, ex[r]);
        #pragma unroll
        for (int o = 8; o; o >>= 1) m = fmaxf(m, __shfl_xor_sync(0xFFFFFFFFu, m, o));
        float ssum = 0.f;
        #pragma unroll
        for (int cc = 0; cc < 4; cc++) { w[r][cc] = expf(w[r][cc] - m); ssum += w[r][cc]; }
        if (hasex) { ex[r] = expf(ex[r] - m); ssum += ex[r]; }
        #pragma unroll
        for (int o = 8; o; o >>= 1) ssum += __shfl_xor_sync(0xFFFFFFFFu, ssum, o);
        float inv = 1.f / ssum;
        #pragma unroll
        for (int cc = 0; cc < 4; cc++) w[r][cc] *= inv;
        if (hasex) ex[r] *= inv;
    }

    __syncthreads();   // all qs_t / ks_t reads complete before overlay writes

    // ---- write weights to dt[j][i] (region B); gather v -> vs (region A) ----
    #pragma unroll
    for (int cc = 0; cc < 4; cc++) {
        float4 o4 = make_float4(w[0][cc], w[1][cc], w[2][cc], w[3][cc]);
        *reinterpret_cast<float4*>(&dt[(c0 + cc) * 68 + r0]) = o4;
    }
    if (hasex) {
        float4 o4 = make_float4(ex[0], ex[1], ex[2], ex[3]);
        *reinterpret_cast<float4*>(&dt[(64 + tx) * 68 + r0]) = o4;
    }
    {
        int cg = tid & 3;
        for (int row = tid >> 2; row < 68; row += 64) {
            const float* sv = (row < 4)
                ? mv + ((size_t)(h * NC_ + c) * M_ + row) * D_
                : v  + ((size_t)bh * T_ + ki[row - 4]) * D_;
            #pragma unroll
            for (int u = 0; u < 4; u++) {
                int d0 = cg * 16 + u * 4;
                float4 b = *reinterpret_cast<const float4*>(sv + d0);
                *reinterpret_cast<float4*>(&vs[row * 64 + d0]) = b;
            }
        }
    }
    __syncthreads();

    // ---- attn @ vf, scatter scaled float4 atomics ----
    {
        unsigned long long a00=0, a01=0, a10=0, a11=0, a20=0, a21=0, a30=0, a31=0;
        #pragma unroll 4
        for (int j = 0; j < 68; j++) {
            float4 a4 = *reinterpret_cast<const float4*>(&dt[j * 68 + r0]);
            ulonglong2 v2 = *reinterpret_cast<const ulonglong2*>(&vs[j * 64 + c0]);
            unsigned long long p0 = pack2(a4.x, a4.x);
            unsigned long long p1 = pack2(a4.y, a4.y);
            unsigned long long p2 = pack2(a4.z, a4.z);
            unsigned long long p3 = pack2(a4.w, a4.w);
            a00 = fma2(p0, v2.x, a00); a01 = fma2(p0, v2.y, a01);
            a10 = fma2(p1, v2.x, a10); a11 = fma2(p1, v2.y, a11);
            a20 = fma2(p2, v2.x, a20); a21 = fma2(p2, v2.y, a21);
            a30 = fma2(p3, v2.x, a30); a31 = fma2(p3, v2.y, a31);
        }
        unsigned long long accs[4][2] = {{a00,a01},{a10,a11},{a20,a21},{a30,a31}};
        #pragma unroll
        for (int r = 0; r < 4; r++) {
            float4 o4;
            unpack2(accs[r][0], o4.x, o4.y);
            unpack2(accs[r][1], o4.z, o4.w);
            float sc2 = sinv[r0 + r];
            o4.x *= sc2; o4.y *= sc2; o4.z *= sc2; o4.w *= sc2;
            float* dst = &out[((size_t)bh * T_ + qi[r0 + r]) * D_ + c0];
            atomicAdd(reinterpret_cast<float4*>(dst), o4);
        }
    }
}

// ---------------------------------------------------------------------------
// Kernel 4: aux loss scalar only
// ---------------------------------------------------------------------------
__global__ void aux_kernel(float* __restrict__ out) {
    out[OUT_ELEMS] = (float)(g_aux * (1.0 / ((double)B_ * H_ * 2 * T_ * D_)) * 0.0001);
}

// ---------------------------------------------------------------------------
extern "C" void kernel_launch(void* const* d_in, const int* in_sizes, int n_in,
                              void* d_out, int out_size) {
    const float* q     = (const float*)d_in[0];
    const float* k     = (const float*)d_in[1];
    const float* v     = (const float*)d_in[2];
    const float* means = (const float*)d_in[3];
    const float* mk    = (const float*)d_in[4];
    const float* mv    = (const float*)d_in[5];
    float* out = (float*)d_out;

    cudaFuncSetAttribute(attn_kernel, cudaFuncAttributeMaxDynamicSharedMemorySize, ATTN_SMEM);

    const int nblk4 = (int)((OUT_ELEMS / 4 + 255) / 256);
    zero_kernel<<<nblk4, 256>>>(out);

    dim3 g1(TT_ / 256, BH_);
    dist_kernel<<<g1, 256>>>(q, k, means);

    select_kernel<<<BH_ * 2 * NC_, 512>>>();

    attn_kernel<<<BH_ * NC_, 256, ATTN_SMEM>>>(q, k, v, mk, mv, out);

    aux_kernel<<<1, 1>>>(out);
}

// round 16
// speedup vs baseline: 1.1535x; 1.1535x over previous
#include <cuda_runtime.h>
#include <math.h>

#define B_ 2
#define T_ 8192
#define H_ 8
#define D_ 64
#define NC_ 128
#define M_ 4
#define W_ 64
#define BH_ (B_*H_)
#define TT_ (2*T_)
#define OUT_ELEMS ((size_t)B_*H_*T_*D_)

__device__ float              g_score[(size_t)BH_*2*NC_*T_];   // 128 MB
__device__ int                g_qidx[BH_*NC_*W_];
__device__ int                g_kidx[BH_*NC_*W_];
__device__ int                g_cnt[BH_*T_];
__device__ double             g_aux;

// ---- f32x2 helpers (sm_100+) ---- (attn only; dist numerics frozen scalar)
__device__ __forceinline__ unsigned long long pack2(float lo, float hi) {
    unsigned long long r;
    asm("mov.b64 %0, {%1,%2};" : "=l"(r) : "f"(lo), "f"(hi));
    return r;
}
__device__ __forceinline__ unsigned long long fma2(unsigned long long a, unsigned long long b, unsigned long long c) {
    unsigned long long d;
    asm("fma.rn.f32x2 %0, %1, %2, %3;" : "=l"(d) : "l"(a), "l"(b), "l"(c));
    return d;
}
__device__ __forceinline__ void unpack2(unsigned long long v, float& lo, float& hi) {
    asm("mov.b64 {%0,%1}, %2;" : "=f"(lo), "=f"(hi) : "l"(v));
}

// ---------------------------------------------------------------------------
// Kernel 0: zero output (atomic target), counts, aux  (R10 verbatim)
// ---------------------------------------------------------------------------
__global__ __launch_bounds__(256) void zero_kernel(float* __restrict__ out) {
    size_t i = (size_t)blockIdx.x * 256 + threadIdx.x;
    if (i < OUT_ELEMS / 4) reinterpret_cast<float4*>(out)[i] = make_float4(0.f, 0.f, 0.f, 0.f);
    if (i < (size_t)BH_ * T_) g_cnt[i] = 0;
    if (i == 0) g_aux = 0.0;
}

// ---------------------------------------------------------------------------
// Kernel 1 — FROZEN R2 scalar arithmetic, R10-proven unroll 2. DO NOT TOUCH.
// (fast-math reassociation means ANY source restructure can change the FFMA
//  tree; R3/R4/R6 failed this way.)
// ---------------------------------------------------------------------------
__global__ __launch_bounds__(256) void dist_kernel(const float* __restrict__ q,
                                                   const float* __restrict__ k,
                                                   const float* __restrict__ means) {
    __shared__ float sm[NC_ * D_];
    __shared__ float sm2[NC_];
    __shared__ float sred[256];
    const int tid = threadIdx.x;
    const int bh  = blockIdx.y;
    const int h   = bh & (H_ - 1);

    const float* mp = means + (size_t)h * NC_ * D_;
    for (int i = tid; i < NC_ * D_; i += 256) sm[i] = mp[i];
    __syncthreads();
    if (tid < NC_) {
        float s = 0.f;
        #pragma unroll
        for (int d = 0; d < D_; d++) { float m = sm[tid * D_ + d]; s += m * m; }
        sm2[tid] = s;
    }
    __syncthreads();

    const int tt   = blockIdx.x * 256 + tid;          // 0 .. 16383
    const int side = (tt >= T_) ? 1 : 0;
    const int tok  = tt - side * T_;
    const float* src = (side ? k : q) + ((size_t)bh * T_ + tok) * D_;

    float x[D_];
    float x2r = 0.f;
    #pragma unroll
    for (int i = 0; i < 16; i++) {
        float4 v = *reinterpret_cast<const float4*>(src + i * 4);
        x[i*4+0] = v.x; x[i*4+1] = v.y; x[i*4+2] = v.z; x[i*4+3] = v.w;
        x2r += v.x*v.x + v.y*v.y + v.z*v.z + v.w*v.w;
    }
    const float s = 1.f / (__fsqrt_rn(x2r) + 1e-6f);
    #pragma unroll
    for (int i = 0; i < D_; i++) x[i] *= s;
    float x2 = 0.f;
    #pragma unroll
    for (int i = 0; i < D_; i++) x2 += x[i] * x[i];

    float* srow = g_score + ((size_t)(bh * 2 + side) * NC_) * T_ + tok;
    float mind2 = 3.402823466e38f;
    #pragma unroll 2
    for (int c = 0; c < NC_; c++) {
        const float4* mr = reinterpret_cast<const float4*>(sm + c * D_);
        float dot = 0.f;
        #pragma unroll
        for (int i = 0; i < 16; i++) {
            float4 m4 = mr[i];
            dot += x[i*4+0]*m4.x + x[i*4+1]*m4.y + x[i*4+2]*m4.z + x[i*4+3]*m4.w;
        }
        float d2 = fmaxf((x2 + sm2[c]) - 2.f * dot, 0.f);
        srow[(size_t)c * T_] = d2;
        mind2 = fminf(mind2, d2);
    }

    sred[tid] = mind2;
    __syncthreads();
    for (int o = 128; o > 0; o >>= 1) {
        if (tid < o) sred[tid] += sred[tid + o];
        __syncthreads();
    }
    if (tid == 0) atomicAdd(&g_aux, (double)sred[0]);
}

// ---------------------------------------------------------------------------
// Kernel 2: exact top-64 — R9/R10 structure (256 thr x 32 elems, frozen per-
// element loops). ONLY change vs R10: bisection stops early at range<=32 and
// the refinement window widens to [lo-16, hi+16] (provably covers all sqrt
// ties of the true V64; unconditional set still <=63 elements).
// ---------------------------------------------------------------------------
__global__ __launch_bounds__(256) void select_kernel() {
    __shared__ unsigned long long cand[2048];
    __shared__ int selIdx[64];
    __shared__ int s_wcnt[8];
    __shared__ unsigned s_wmn[8], s_wmx[8];
    __shared__ unsigned s_lo, s_hi;
    __shared__ int s_nsel, s_ncand;
    __shared__ unsigned long long s_wmin[8], s_min;

    const int tid  = threadIdx.x;
    const int lane = tid & 31, wid = tid >> 5;
    const int c    = blockIdx.x & (NC_ - 1);
    const int side = (blockIdx.x >> 7) & 1;
    const int bh   = blockIdx.x >> 8;
    const float* sc = g_score + ((size_t)((bh * 2 + side) * NC_ + c)) * T_;

    if (tid == 0) { s_nsel = 0; s_ncand = 0; }

    unsigned ord[32];
    unsigned mn = 0xFFFFFFFFu, mx = 0u;
    #pragma unroll
    for (int j = 0; j < 32; j++) {
        unsigned u = __float_as_uint(sc[tid + j * 256]) | 0x80000000u;  // d2>=0
        ord[j] = u;
        mn = min(mn, u); mx = max(mx, u);
    }
    #pragma unroll
    for (int o = 16; o; o >>= 1) {
        mn = min(mn, __shfl_xor_sync(0xFFFFFFFFu, mn, o));
        mx = max(mx, __shfl_xor_sync(0xFFFFFFFFu, mx, o));
    }
    if (lane == 0) { s_wmn[wid] = mn; s_wmx[wid] = mx; }
    __syncthreads();
    if (tid == 0) {
        unsigned glo = s_wmn[0], ghi = s_wmx[0];
        for (int w2 = 1; w2 < 8; w2++) { glo = min(glo, s_wmn[w2]); ghi = max(ghi, s_wmx[w2]); }
        s_lo = glo; s_hi = ghi;
    }
    __syncthreads();

    // ---- 2-way bisection, early stop at range<=32 (lo <= V64 <= hi) ----
    while (true) {
        unsigned lo = s_lo, hi = s_hi;
        if (hi - lo <= 32u) break;
        unsigned mid = lo + ((hi - lo) >> 1);
        int cnt = 0;
        #pragma unroll
        for (int j = 0; j < 32; j++) cnt += (ord[j] <= mid) ? 1 : 0;
        #pragma unroll
        for (int o = 16; o; o >>= 1) cnt += __shfl_xor_sync(0xFFFFFFFFu, cnt, o);
        if (lane == 0) s_wcnt[wid] = cnt;
        __syncthreads();
        if (tid == 0) {
            int t = 0;
            for (int w2 = 0; w2 < 8; w2++) t += s_wcnt[w2];
            if (t >= W_) s_hi = mid; else s_lo = mid + 1;
        }
        __syncthreads();
    }
    const unsigned Vlo = s_lo, Vhi = s_hi;      // Vlo <= V64 <= Vhi
    const unsigned lowcut  = (Vlo >= 0x80000010u) ? (Vlo - 16u) : 0x80000000u;
    const unsigned highcut = (Vhi <= 0xFFFFFFEFu) ? (Vhi + 16u) : 0xFFFFFFFFu;

    // ---- classify (frozen loop structure) ----
    #pragma unroll
    for (int j = 0; j < 32; j++) {
        unsigned u = ord[j];
        if (u < lowcut) {
            selIdx[atomicAdd(&s_nsel, 1)] = tid + j * 256;
        } else if (u <= highcut) {
            int p = atomicAdd(&s_ncand, 1);
            if (p < 2048) {
                float d2v = __uint_as_float(u & 0x7FFFFFFFu);
                unsigned sq = __float_as_uint(__fsqrt_rn(d2v));
                cand[p] = ((unsigned long long)sq << 32) | (unsigned)(tid + j * 256);
            }
        }
    }
    __syncthreads();

    const int nbelow = s_nsel;
    const int r = W_ - nbelow;
    const int ncand = min(s_ncand, 2048);
    for (int it = 0; it < r; it++) {
        unsigned long long mv = 0xFFFFFFFFFFFFFFFFull;
        for (int p = tid; p < ncand; p += 256) {
            unsigned long long cv = cand[p];
            if (cv < mv) mv = cv;
        }
        #pragma unroll
        for (int o = 16; o; o >>= 1) {
            unsigned long long ov = __shfl_down_sync(0xFFFFFFFFu, mv, o);
            if (ov < mv) mv = ov;
        }
        if (lane == 0) s_wmin[wid] = mv;
        __syncthreads();
        if (tid == 0) {
            unsigned long long m = s_wmin[0];
            for (int w2 = 1; w2 < 8; w2++) if (s_wmin[w2] < m) m = s_wmin[w2];
            s_min = m;
            selIdx[nbelow + it] = (int)(m & 0xFFFFFFFFull);
        }
        __syncthreads();
        unsigned long long m = s_min;
        for (int p = tid; p < ncand; p += 256)
            if (cand[p] == m) cand[p] = 0xFFFFFFFFFFFFFFFFull;
        __syncthreads();
    }

    int* dst = (side == 0 ? g_qidx : g_kidx) + (bh * NC_ + c) * W_;
    if (tid < W_) {
        int idx = selIdx[tid];
        dst[tid] = idx;
        if (side == 0) atomicAdd(&g_cnt[bh * T_ + idx], 1);
    }
}

// ---------------------------------------------------------------------------
// Kernel 3 (R10 verbatim): attention with phase-overlaid smem (36KB).
// ---------------------------------------------------------------------------
#define A_OFF    0
#define B_OFF    4352
#define INT_OFF  (4352 + 4624)
#define ATTN_SMEM ((INT_OFF + 192) * 4)

__global__ __launch_bounds__(256) void attn_kernel(const float* __restrict__ q,
                                                   const float* __restrict__ k,
                                                   const float* __restrict__ v,
                                                   const float* __restrict__ mk,
                                                   const float* __restrict__ mv,
                                                   float* __restrict__ out) {
    extern __shared__ float sf[];
    float* ks_t = sf + A_OFF;     // [d][j] pitch 68   (QK phase)
    float* vs   = sf + A_OFF;     // [j][dd] pitch 64  (AV phase)
    float* qs_t = sf + B_OFF;     // [d][row] pitch 68 (QK phase)
    float* dt   = sf + B_OFF;     // [j][i]  pitch 68  (AV phase)
    int*   qi   = (int*)(sf + INT_OFF);
    int*   ki   = qi + 64;
    float* sinv = (float*)(ki + 64);

    const int tid = threadIdx.x;
    const int c   = blockIdx.x & (NC_ - 1);
    const int bh  = blockIdx.x >> 7;
    const int h   = bh & (H_ - 1);

    if (tid < 64) {
        int qv = g_qidx[(bh * NC_ + c) * W_ + tid];
        qi[tid] = qv;
        ki[tid] = g_kidx[(bh * NC_ + c) * W_ + tid];
        sinv[tid] = 1.0f / ((float)g_cnt[bh * T_ + qv] + 1e-5f);
    }
    __syncthreads();

    // ---- gather q -> qs_t (transposed) ----
    {
        int row = tid >> 2, cg = tid & 3;
        const float* src = q + ((size_t)bh * T_ + qi[row]) * D_ + cg * 16;
        #pragma unroll
        for (int u = 0; u < 4; u++) {
            float4 t4 = *reinterpret_cast<const float4*>(src + u * 4);
            int d0 = cg * 16 + u * 4;
            qs_t[(d0+0)*68 + row] = t4.x;
            qs_t[(d0+1)*68 + row] = t4.y;
            qs_t[(d0+2)*68 + row] = t4.z;
            qs_t[(d0+3)*68 + row] = t4.w;
        }
    }
    // ---- gather kf -> ks_t (transposed); rows 0..3 = memory keys ----
    {
        int cg = tid & 3;
        for (int row = tid >> 2; row < 68; row += 64) {
            const float* sk = (row < 4)
                ? mk + ((size_t)(h * NC_ + c) * M_ + row) * D_
                : k  + ((size_t)bh * T_ + ki[row - 4]) * D_;
            #pragma unroll
            for (int u = 0; u < 4; u++) {
                int d0 = cg * 16 + u * 4;
                float4 a = *reinterpret_cast<const float4*>(sk + d0);
                ks_t[(d0+0)*68 + row] = a.x;
                ks_t[(d0+1)*68 + row] = a.y;
                ks_t[(d0+2)*68 + row] = a.z;
                ks_t[(d0+3)*68 + row] = a.w;
            }
        }
    }
    __syncthreads();

    const int tx = tid & 15, ty = tid >> 4;
    const int r0 = 4 * ty, c0 = 4 * tx;

    // ---- QK^T main tile -> registers w[r][c] ----
    float w[4][4];
    {
        unsigned long long a00=0, a01=0, a10=0, a11=0, a20=0, a21=0, a30=0, a31=0;
        #pragma unroll 8
        for (int d = 0; d < D_; d++) {
            float4 q4 = *reinterpret_cast<const float4*>(&qs_t[d * 68 + r0]);
            ulonglong2 k2 = *reinterpret_cast<const ulonglong2*>(&ks_t[d * 68 + c0]);
            unsigned long long p0 = pack2(q4.x, q4.x);
            unsigned long long p1 = pack2(q4.y, q4.y);
            unsigned long long p2 = pack2(q4.z, q4.z);
            unsigned long long p3 = pack2(q4.w, q4.w);
            a00 = fma2(p0, k2.x, a00); a01 = fma2(p0, k2.y, a01);
            a10 = fma2(p1, k2.x, a10); a11 = fma2(p1, k2.y, a11);
            a20 = fma2(p2, k2.x, a20); a21 = fma2(p2, k2.y, a21);
            a30 = fma2(p3, k2.x, a30); a31 = fma2(p3, k2.y, a31);
        }
        unpack2(a00, w[0][0], w[0][1]); unpack2(a01, w[0][2], w[0][3]);
        unpack2(a10, w[1][0], w[1][1]); unpack2(a11, w[1][2], w[1][3]);
        unpack2(a20, w[2][0], w[2][1]); unpack2(a21, w[2][2], w[2][3]);
        unpack2(a30, w[3][0], w[3][1]); unpack2(a31, w[3][2], w[3][3]);
        #pragma unroll
        for (int r = 0; r < 4; r++)
            #pragma unroll
            for (int cc = 0; cc < 4; cc++) w[r][cc] *= 0.125f;
    }

    // ---- extra cols 64..67 (memory keys): lanes tx<4 ----
    float ex[4] = {0.f, 0.f, 0.f, 0.f};
    const bool hasex = (tx < 4);
    if (hasex) {
        const int jm = 64 + tx;
        #pragma unroll 8
        for (int d = 0; d < D_; d++) {
            float4 q4 = *reinterpret_cast<const float4*>(&qs_t[d * 68 + r0]);
            float kv = ks_t[d * 68 + jm];
            ex[0] += q4.x * kv; ex[1] += q4.y * kv;
            ex[2] += q4.z * kv; ex[3] += q4.w * kv;
        }
        #pragma unroll
        for (int r = 0; r < 4; r++) ex[r] *= 0.125f;
    }

    // ---- row softmax in registers (rows owned by 16 tx lanes) ----
    #pragma unroll
    for (int r = 0; r < 4; r++) {
        float m = fmaxf(fmaxf(w[r][0], w[r][1]), fmaxf(w[r][2], w[r][3]));
        if (hasex) m = fmaxf(m, ex[r]);
        #pragma unroll
        for (int o = 8; o; o >>= 1) m = fmaxf(m, __shfl_xor_sync(0xFFFFFFFFu, m, o));
        float ssum = 0.f;
        #pragma unroll
        for (int cc = 0; cc < 4; cc++) { w[r][cc] = expf(w[r][cc] - m); ssum += w[r][cc]; }
        if (hasex) { ex[r] = expf(ex[r] - m); ssum += ex[r]; }
        #pragma unroll
        for (int o = 8; o; o >>= 1) ssum += __shfl_xor_sync(0xFFFFFFFFu, ssum, o);
        float inv = 1.f / ssum;
        #pragma unroll
        for (int cc = 0; cc < 4; cc++) w[r][cc] *= inv;
        if (hasex) ex[r] *= inv;
    }

    __syncthreads();   // all qs_t / ks_t reads complete before overlay writes

    // ---- write weights to dt[j][i] (region B); gather v -> vs (region A) ----
    #pragma unroll
    for (int cc = 0; cc < 4; cc++) {
        float4 o4 = make_float4(w[0][cc], w[1][cc], w[2][cc], w[3][cc]);
        *reinterpret_cast<float4*>(&dt[(c0 + cc) * 68 + r0]) = o4;
    }
    if (hasex) {
        float4 o4 = make_float4(ex[0], ex[1], ex[2], ex[3]);
        *reinterpret_cast<float4*>(&dt[(64 + tx) * 68 + r0]) = o4;
    }
    {
        int cg = tid & 3;
        for (int row = tid >> 2; row < 68; row += 64) {
            const float* sv = (row < 4)
                ? mv + ((size_t)(h * NC_ + c) * M_ + row) * D_
                : v  + ((size_t)bh * T_ + ki[row - 4]) * D_;
            #pragma unroll
            for (int u = 0; u < 4; u++) {
                int d0 = cg * 16 + u * 4;
                float4 b = *reinterpret_cast<const float4*>(sv + d0);
                *reinterpret_cast<float4*>(&vs[row * 64 + d0]) = b;
            }
        }
    }
    __syncthreads();

    // ---- attn @ vf, scatter scaled float4 atomics ----
    {
        unsigned long long a00=0, a01=0, a10=0, a11=0, a20=0, a21=0, a30=0, a31=0;
        #pragma unroll 4
        for (int j = 0; j < 68; j++) {
            float4 a4 = *reinterpret_cast<const float4*>(&dt[j * 68 + r0]);
            ulonglong2 v2 = *reinterpret_cast<const ulonglong2*>(&vs[j * 64 + c0]);
            unsigned long long p0 = pack2(a4.x, a4.x);
            unsigned long long p1 = pack2(a4.y, a4.y);
            unsigned long long p2 = pack2(a4.z, a4.z);
            unsigned long long p3 = pack2(a4.w, a4.w);
            a00 = fma2(p0, v2.x, a00); a01 = fma2(p0, v2.y, a01);
            a10 = fma2(p1, v2.x, a10); a11 = fma2(p1, v2.y, a11);
            a20 = fma2(p2, v2.x, a20); a21 = fma2(p2, v2.y, a21);
            a30 = fma2(p3, v2.x, a30); a31 = fma2(p3, v2.y, a31);
        }
        unsigned long long accs[4][2] = {{a00,a01},{a10,a11},{a20,a21},{a30,a31}};
        #pragma unroll
        for (int r = 0; r < 4; r++) {
            float4 o4;
            unpack2(accs[r][0], o4.x, o4.y);
            unpack2(accs[r][1], o4.z, o4.w);
            float sc2 = sinv[r0 + r];
            o4.x *= sc2; o4.y *= sc2; o4.z *= sc2; o4.w *= sc2;
            float* dst = &out[((size_t)bh * T_ + qi[r0 + r]) * D_ + c0];
            atomicAdd(reinterpret_cast<float4*>(dst), o4);
        }
    }
}

// ---------------------------------------------------------------------------
// Kernel 4: aux loss scalar only
// ---------------------------------------------------------------------------
__global__ void aux_kernel(float* __restrict__ out) {
    out[OUT_ELEMS] = (float)(g_aux * (1.0 / ((double)B_ * H_ * 2 * T_ * D_)) * 0.0001);
}

// ---------------------------------------------------------------------------
extern "C" void kernel_launch(void* const* d_in, const int* in_sizes, int n_in,
                              void* d_out, int out_size) {
    const float* q     = (const float*)d_in[0];
    const float* k     = (const float*)d_in[1];
    const float* v     = (const float*)d_in[2];
    const float* means = (const float*)d_in[3];
    const float* mk    = (const float*)d_in[4];
    const float* mv    = (const float*)d_in[5];
    float* out = (float*)d_out;

    cudaFuncSetAttribute(attn_kernel, cudaFuncAttributeMaxDynamicSharedMemorySize, ATTN_SMEM);

    const int nblk4 = (int)((OUT_ELEMS / 4 + 255) / 256);
    zero_kernel<<<nblk4, 256>>>(out);

    dim3 g1(TT_ / 256, BH_);
    dist_kernel<<<g1, 256>>>(q, k, means);

    select_kernel<<<BH_ * 2 * NC_, 256>>>();

    attn_kernel<<<BH_ * NC_, 256, ATTN_SMEM>>>(q, k, v, mk, mv, out);

    aux_kernel<<<1, 1>>>(out);
}

// round 17
// speedup vs baseline: 1.1651x; 1.0100x over previous
#include <cuda_runtime.h>
#include <math.h>

#define B_ 2
#define T_ 8192
#define H_ 8
#define D_ 64
#define NC_ 128
#define M_ 4
#define W_ 64
#define BH_ (B_*H_)
#define TT_ (2*T_)
#define OUT_ELEMS ((size_t)B_*H_*T_*D_)

__device__ float              g_score[(size_t)BH_*2*NC_*T_];   // 128 MB
__device__ int                g_qidx[BH_*NC_*W_];
__device__ int                g_kidx[BH_*NC_*W_];
__device__ int                g_cnt[BH_*T_];
__device__ double             g_aux;

// ---- f32x2 helpers (sm_100+) ---- (attn only; dist numerics frozen scalar)
__device__ __forceinline__ unsigned long long pack2(float lo, float hi) {
    unsigned long long r;
    asm("mov.b64 %0, {%1,%2};" : "=l"(r) : "f"(lo), "f"(hi));
    return r;
}
__device__ __forceinline__ unsigned long long fma2(unsigned long long a, unsigned long long b, unsigned long long c) {
    unsigned long long d;
    asm("fma.rn.f32x2 %0, %1, %2, %3;" : "=l"(d) : "l"(a), "l"(b), "l"(c));
    return d;
}
__device__ __forceinline__ void unpack2(unsigned long long v, float& lo, float& hi) {
    asm("mov.b64 {%0,%1}, %2;" : "=f"(lo), "=f"(hi) : "l"(v));
}

// ---------------------------------------------------------------------------
// Kernel 0: zero output (atomic target), counts, aux  (R10 verbatim)
// ---------------------------------------------------------------------------
__global__ __launch_bounds__(256) void zero_kernel(float* __restrict__ out) {
    size_t i = (size_t)blockIdx.x * 256 + threadIdx.x;
    if (i < OUT_ELEMS / 4) reinterpret_cast<float4*>(out)[i] = make_float4(0.f, 0.f, 0.f, 0.f);
    if (i < (size_t)BH_ * T_) g_cnt[i] = 0;
    if (i == 0) g_aux = 0.0;
}

// ---------------------------------------------------------------------------
// Kernel 1 — FROZEN R2 scalar arithmetic, R10-proven unroll 2. DO NOT TOUCH.
// ---------------------------------------------------------------------------
__global__ __launch_bounds__(256) void dist_kernel(const float* __restrict__ q,
                                                   const float* __restrict__ k,
                                                   const float* __restrict__ means) {
    __shared__ float sm[NC_ * D_];
    __shared__ float sm2[NC_];
    __shared__ float sred[256];
    const int tid = threadIdx.x;
    const int bh  = blockIdx.y;
    const int h   = bh & (H_ - 1);

    const float* mp = means + (size_t)h * NC_ * D_;
    for (int i = tid; i < NC_ * D_; i += 256) sm[i] = mp[i];
    __syncthreads();
    if (tid < NC_) {
        float s = 0.f;
        #pragma unroll
        for (int d = 0; d < D_; d++) { float m = sm[tid * D_ + d]; s += m * m; }
        sm2[tid] = s;
    }
    __syncthreads();

    const int tt   = blockIdx.x * 256 + tid;          // 0 .. 16383
    const int side = (tt >= T_) ? 1 : 0;
    const int tok  = tt - side * T_;
    const float* src = (side ? k : q) + ((size_t)bh * T_ + tok) * D_;

    float x[D_];
    float x2r = 0.f;
    #pragma unroll
    for (int i = 0; i < 16; i++) {
        float4 v = *reinterpret_cast<const float4*>(src + i * 4);
        x[i*4+0] = v.x; x[i*4+1] = v.y; x[i*4+2] = v.z; x[i*4+3] = v.w;
        x2r += v.x*v.x + v.y*v.y + v.z*v.z + v.w*v.w;
    }
    const float s = 1.f / (__fsqrt_rn(x2r) + 1e-6f);
    #pragma unroll
    for (int i = 0; i < D_; i++) x[i] *= s;
    float x2 = 0.f;
    #pragma unroll
    for (int i = 0; i < D_; i++) x2 += x[i] * x[i];

    float* srow = g_score + ((size_t)(bh * 2 + side) * NC_) * T_ + tok;
    float mind2 = 3.402823466e38f;
    #pragma unroll 2
    for (int c = 0; c < NC_; c++) {
        const float4* mr = reinterpret_cast<const float4*>(sm + c * D_);
        float dot = 0.f;
        #pragma unroll
        for (int i = 0; i < 16; i++) {
            float4 m4 = mr[i];
            dot += x[i*4+0]*m4.x + x[i*4+1]*m4.y + x[i*4+2]*m4.z + x[i*4+3]*m4.w;
        }
        float d2 = fmaxf((x2 + sm2[c]) - 2.f * dot, 0.f);
        srow[(size_t)c * T_] = d2;
        mind2 = fminf(mind2, d2);
    }

    sred[tid] = mind2;
    __syncthreads();
    for (int o = 128; o > 0; o >>= 1) {
        if (tid < o) sred[tid] += sred[tid + o];
        __syncthreads();
    }
    if (tid == 0) atomicAdd(&g_aux, (double)sred[0]);
}

// ---------------------------------------------------------------------------
// Kernel 2: exact top-64 — R16 logic (early-stop bisection, window refine).
// ONLY change vs R16: hi seeds from min-over-warps of (max-over-lanes of
// lane-2nd-smallest), a provable upper bound on V64 (>=64 elements <= bound
// within each single warp), shrinking the initial range by ~2^8.
// ---------------------------------------------------------------------------
__global__ __launch_bounds__(256) void select_kernel() {
    __shared__ unsigned long long cand[2048];
    __shared__ int selIdx[64];
    __shared__ int s_wcnt[8];
    __shared__ unsigned s_wmn[8], s_wmx[8];
    __shared__ unsigned s_lo, s_hi;
    __shared__ int s_nsel, s_ncand;
    __shared__ unsigned long long s_wmin[8], s_min;

    const int tid  = threadIdx.x;
    const int lane = tid & 31, wid = tid >> 5;
    const int c    = blockIdx.x & (NC_ - 1);
    const int side = (blockIdx.x >> 7) & 1;
    const int bh   = blockIdx.x >> 8;
    const float* sc = g_score + ((size_t)((bh * 2 + side) * NC_ + c)) * T_;

    if (tid == 0) { s_nsel = 0; s_ncand = 0; }

    // ---- load 32 elements; track lane 2 smallest (m1 <= m2) ----
    unsigned ord[32];
    unsigned m1 = 0xFFFFFFFFu, m2 = 0xFFFFFFFFu;
    #pragma unroll
    for (int j = 0; j < 32; j++) {
        unsigned u = __float_as_uint(sc[tid + j * 256]) | 0x80000000u;  // d2>=0
        ord[j] = u;
        if (u < m1) { m2 = m1; m1 = u; }
        else if (u < m2) { m2 = u; }
    }
    // warp: lo-part = min over lanes of m1 (true warp min);
    //       hi-part = max over lanes of m2 (valid V64 upper bound per warp)
    unsigned wmn = m1, wub = m2;
    #pragma unroll
    for (int o = 16; o; o >>= 1) {
        wmn = min(wmn, __shfl_xor_sync(0xFFFFFFFFu, wmn, o));
        wub = max(wub, __shfl_xor_sync(0xFFFFFFFFu, wub, o));
    }
    if (lane == 0) { s_wmn[wid] = wmn; s_wmx[wid] = wub; }
    __syncthreads();
    if (tid == 0) {
        unsigned glo = s_wmn[0], ghi = s_wmx[0];
        for (int w2 = 1; w2 < 8; w2++) { glo = min(glo, s_wmn[w2]); ghi = min(ghi, s_wmx[w2]); }
        s_lo = glo; s_hi = ghi;     // glo <= V64 <= ghi
    }
    __syncthreads();

    // ---- 2-way bisection, early stop at range<=32 (lo <= V64 <= hi) ----
    while (true) {
        unsigned lo = s_lo, hi = s_hi;
        if (hi - lo <= 32u) break;
        unsigned mid = lo + ((hi - lo) >> 1);
        int cnt = 0;
        #pragma unroll
        for (int j = 0; j < 32; j++) cnt += (ord[j] <= mid) ? 1 : 0;
        #pragma unroll
        for (int o = 16; o; o >>= 1) cnt += __shfl_xor_sync(0xFFFFFFFFu, cnt, o);
        if (lane == 0) s_wcnt[wid] = cnt;
        __syncthreads();
        if (tid == 0) {
            int t = 0;
            for (int w2 = 0; w2 < 8; w2++) t += s_wcnt[w2];
            if (t >= W_) s_hi = mid; else s_lo = mid + 1;
        }
        __syncthreads();
    }
    const unsigned Vlo = s_lo, Vhi = s_hi;      // Vlo <= V64 <= Vhi
    const unsigned lowcut  = (Vlo >= 0x80000010u) ? (Vlo - 16u) : 0x80000000u;
    const unsigned highcut = (Vhi <= 0xFFFFFFEFu) ? (Vhi + 16u) : 0xFFFFFFFFu;

    // ---- classify (frozen loop structure) ----
    #pragma unroll
    for (int j = 0; j < 32; j++) {
        unsigned u = ord[j];
        if (u < lowcut) {
            selIdx[atomicAdd(&s_nsel, 1)] = tid + j * 256;
        } else if (u <= highcut) {
            int p = atomicAdd(&s_ncand, 1);
            if (p < 2048) {
                float d2v = __uint_as_float(u & 0x7FFFFFFFu);
                unsigned sq = __float_as_uint(__fsqrt_rn(d2v));
                cand[p] = ((unsigned long long)sq << 32) | (unsigned)(tid + j * 256);
            }
        }
    }
    __syncthreads();

    const int nbelow = s_nsel;
    const int r = W_ - nbelow;
    const int ncand = min(s_ncand, 2048);
    for (int it = 0; it < r; it++) {
        unsigned long long mv = 0xFFFFFFFFFFFFFFFFull;
        for (int p = tid; p < ncand; p += 256) {
            unsigned long long cv = cand[p];
            if (cv < mv) mv = cv;
        }
        #pragma unroll
        for (int o = 16; o; o >>= 1) {
            unsigned long long ov = __shfl_down_sync(0xFFFFFFFFu, mv, o);
            if (ov < mv) mv = ov;
        }
        if (lane == 0) s_wmin[wid] = mv;
        __syncthreads();
        if (tid == 0) {
            unsigned long long m = s_wmin[0];
            for (int w2 = 1; w2 < 8; w2++) if (s_wmin[w2] < m) m = s_wmin[w2];
            s_min = m;
            selIdx[nbelow + it] = (int)(m & 0xFFFFFFFFull);
        }
        __syncthreads();
        unsigned long long m = s_min;
        for (int p = tid; p < ncand; p += 256)
            if (cand[p] == m) cand[p] = 0xFFFFFFFFFFFFFFFFull;
        __syncthreads();
    }

    int* dst = (side == 0 ? g_qidx : g_kidx) + (bh * NC_ + c) * W_;
    if (tid < W_) {
        int idx = selIdx[tid];
        dst[tid] = idx;
        if (side == 0) atomicAdd(&g_cnt[bh * T_ + idx], 1);
    }
}

// ---------------------------------------------------------------------------
// Kernel 3 (R10 verbatim): attention with phase-overlaid smem (36KB).
// ---------------------------------------------------------------------------
#define A_OFF    0
#define B_OFF    4352
#define INT_OFF  (4352 + 4624)
#define ATTN_SMEM ((INT_OFF + 192) * 4)

__global__ __launch_bounds__(256) void attn_kernel(const float* __restrict__ q,
                                                   const float* __restrict__ k,
                                                   const float* __restrict__ v,
                                                   const float* __restrict__ mk,
                                                   const float* __restrict__ mv,
                                                   float* __restrict__ out) {
    extern __shared__ float sf[];
    float* ks_t = sf + A_OFF;     // [d][j] pitch 68   (QK phase)
    float* vs   = sf + A_OFF;     // [j][dd] pitch 64  (AV phase)
    float* qs_t = sf + B_OFF;     // [d][row] pitch 68 (QK phase)
    float* dt   = sf + B_OFF;     // [j][i]  pitch 68  (AV phase)
    int*   qi   = (int*)(sf + INT_OFF);
    int*   ki   = qi + 64;
    float* sinv = (float*)(ki + 64);

    const int tid = threadIdx.x;
    const int c   = blockIdx.x & (NC_ - 1);
    const int bh  = blockIdx.x >> 7;
    const int h   = bh & (H_ - 1);

    if (tid < 64) {
        int qv = g_qidx[(bh * NC_ + c) * W_ + tid];
        qi[tid] = qv;
        ki[tid] = g_kidx[(bh * NC_ + c) * W_ + tid];
        sinv[tid] = 1.0f / ((float)g_cnt[bh * T_ + qv] + 1e-5f);
    }
    __syncthreads();

    // ---- gather q -> qs_t (transposed) ----
    {
        int row = tid >> 2, cg = tid & 3;
        const float* src = q + ((size_t)bh * T_ + qi[row]) * D_ + cg * 16;
        #pragma unroll
        for (int u = 0; u < 4; u++) {
            float4 t4 = *reinterpret_cast<const float4*>(src + u * 4);
            int d0 = cg * 16 + u * 4;
            qs_t[(d0+0)*68 + row] = t4.x;
            qs_t[(d0+1)*68 + row] = t4.y;
            qs_t[(d0+2)*68 + row] = t4.z;
            qs_t[(d0+3)*68 + row] = t4.w;
        }
    }
    // ---- gather kf -> ks_t (transposed); rows 0..3 = memory keys ----
    {
        int cg = tid & 3;
        for (int row = tid >> 2; row < 68; row += 64) {
            const float* sk = (row < 4)
                ? mk + ((size_t)(h * NC_ + c) * M_ + row) * D_
                : k  + ((size_t)bh * T_ + ki[row - 4]) * D_;
            #pragma unroll
            for (int u = 0; u < 4; u++) {
                int d0 = cg * 16 + u * 4;
                float4 a = *reinterpret_cast<const float4*>(sk + d0);
                ks_t[(d0+0)*68 + row] = a.x;
                ks_t[(d0+1)*68 + row] = a.y;
                ks_t[(d0+2)*68 + row] = a.z;
                ks_t[(d0+3)*68 + row] = a.w;
            }
        }
    }
    __syncthreads();

    const int tx = tid & 15, ty = tid >> 4;
    const int r0 = 4 * ty, c0 = 4 * tx;

    // ---- QK^T main tile -> registers w[r][c] ----
    float w[4][4];
    {
        unsigned long long a00=0, a01=0, a10=0, a11=0, a20=0, a21=0, a30=0, a31=0;
        #pragma unroll 8
        for (int d = 0; d < D_; d++) {
            float4 q4 = *reinterpret_cast<const float4*>(&qs_t[d * 68 + r0]);
            ulonglong2 k2 = *reinterpret_cast<const ulonglong2*>(&ks_t[d * 68 + c0]);
            unsigned long long p0 = pack2(q4.x, q4.x);
            unsigned long long p1 = pack2(q4.y, q4.y);
            unsigned long long p2 = pack2(q4.z, q4.z);
            unsigned long long p3 = pack2(q4.w, q4.w);
            a00 = fma2(p0, k2.x, a00); a01 = fma2(p0, k2.y, a01);
            a10 = fma2(p1, k2.x, a10); a11 = fma2(p1, k2.y, a11);
            a20 = fma2(p2, k2.x, a20); a21 = fma2(p2, k2.y, a21);
            a30 = fma2(p3, k2.x, a30); a31 = fma2(p3, k2.y, a31);
        }
        unpack2(a00, w[0][0], w[0][1]); unpack2(a01, w[0][2], w[0][3]);
        unpack2(a10, w[1][0], w[1][1]); unpack2(a11, w[1][2], w[1][3]);
        unpack2(a20, w[2][0], w[2][1]); unpack2(a21, w[2][2], w[2][3]);
        unpack2(a30, w[3][0], w[3][1]); unpack2(a31, w[3][2], w[3][3]);
        #pragma unroll
        for (int r = 0; r < 4; r++)
            #pragma unroll
            for (int cc = 0; cc < 4; cc++) w[r][cc] *= 0.125f;
    }

    // ---- extra cols 64..67 (memory keys): lanes tx<4 ----
    float ex[4] = {0.f, 0.f, 0.f, 0.f};
    const bool hasex = (tx < 4);
    if (hasex) {
        const int jm = 64 + tx;
        #pragma unroll 8
        for (int d = 0; d < D_; d++) {
            float4 q4 = *reinterpret_cast<const float4*>(&qs_t[d * 68 + r0]);
            float kv = ks_t[d * 68 + jm];
            ex[0] += q4.x * kv; ex[1] += q4.y * kv;
            ex[2] += q4.z * kv; ex[3] += q4.w * kv;
        }
        #pragma unroll
        for (int r = 0; r < 4; r++) ex[r] *= 0.125f;
    }

    // ---- row softmax in registers (rows owned by 16 tx lanes) ----
    #pragma unroll
    for (int r = 0; r < 4; r++) {
        float m = fmaxf(fmaxf(w[r][0], w[r][1]), fmaxf(w[r][2], w[r][3]));
        if (hasex) m = fmaxf(m, ex[r]);
        #pragma unroll
        for (int o = 8; o; o >>= 1) m = fmaxf(m, __shfl_xor_sync(0xFFFFFFFFu, m, o));
        float ssum = 0.f;
        #pragma unroll
        for (int cc = 0; cc < 4; cc++) { w[r][cc] = expf(w[r][cc] - m); ssum += w[r][cc]; }
        if (hasex) { ex[r] = expf(ex[r] - m); ssum += ex[r]; }
        #pragma unroll
        for (int o = 8; o; o >>= 1) ssum += __shfl_xor_sync(0xFFFFFFFFu, ssum, o);
        float inv = 1.f / ssum;
        #pragma unroll
        for (int cc = 0; cc < 4; cc++) w[r][cc] *= inv;
        if (hasex) ex[r] *= inv;
    }

    __syncthreads();   // all qs_t / ks_t reads complete before overlay writes

    // ---- write weights to dt[j][i] (region B); gather v -> vs (region A) ----
    #pragma unroll
    for (int cc = 0; cc < 4; cc++) {
        float4 o4 = make_float4(w[0][cc], w[1][cc], w[2][cc], w[3][cc]);
        *reinterpret_cast<float4*>(&dt[(c0 + cc) * 68 + r0]) = o4;
    }
    if (hasex) {
        float4 o4 = make_float4(ex[0], ex[1], ex[2], ex[3]);
        *reinterpret_cast<float4*>(&dt[(64 + tx) * 68 + r0]) = o4;
    }
    {
        int cg = tid & 3;
        for (int row = tid >> 2; row < 68; row += 64) {
            const float* sv = (row < 4)
                ? mv + ((size_t)(h * NC_ + c) * M_ + row) * D_
                : v  + ((size_t)bh * T_ + ki[row - 4]) * D_;
            #pragma unroll
            for (int u = 0; u < 4; u++) {
                int d0 = cg * 16 + u * 4;
                float4 b = *reinterpret_cast<const float4*>(sv + d0);
                *reinterpret_cast<float4*>(&vs[row * 64 + d0]) = b;
            }
        }
    }
    __syncthreads();

    // ---- attn @ vf, scatter scaled float4 atomics ----
    {
        unsigned long long a00=0, a01=0, a10=0, a11=0, a20=0, a21=0, a30=0, a31=0;
        #pragma unroll 4
        for (int j = 0; j < 68; j++) {
            float4 a4 = *reinterpret_cast<const float4*>(&dt[j * 68 + r0]);
            ulonglong2 v2 = *reinterpret_cast<const ulonglong2*>(&vs[j * 64 + c0]);
            unsigned long long p0 = pack2(a4.x, a4.x);
            unsigned long long p1 = pack2(a4.y, a4.y);
            unsigned long long p2 = pack2(a4.z, a4.z);
            unsigned long long p3 = pack2(a4.w, a4.w);
            a00 = fma2(p0, v2.x, a00); a01 = fma2(p0, v2.y, a01);
            a10 = fma2(p1, v2.x, a10); a11 = fma2(p1, v2.y, a11);
            a20 = fma2(p2, v2.x, a20); a21 = fma2(p2, v2.y, a21);
            a30 = fma2(p3, v2.x, a30); a31 = fma2(p3, v2.y, a31);
        }
        unsigned long long accs[4][2] = {{a00,a01},{a10,a11},{a20,a21},{a30,a31}};
        #pragma unroll
        for (int r = 0; r < 4; r++) {
            float4 o4;
            unpack2(accs[r][0], o4.x, o4.y);
            unpack2(accs[r][1], o4.z, o4.w);
            float sc2 = sinv[r0 + r];
            o4.x *= sc2; o4.y *= sc2; o4.z *= sc2; o4.w *= sc2;
            float* dst = &out[((size_t)bh * T_ + qi[r0 + r]) * D_ + c0];
            atomicAdd(reinterpret_cast<float4*>(dst), o4);
        }
    }
}

// ---------------------------------------------------------------------------
// Kernel 4: aux loss scalar only
// ---------------------------------------------------------------------------
__global__ void aux_kernel(float* __restrict__ out) {
    out[OUT_ELEMS] = (float)(g_aux * (1.0 / ((double)B_ * H_ * 2 * T_ * D_)) * 0.0001);
}

// ---------------------------------------------------------------------------
extern "C" void kernel_launch(void* const* d_in, const int* in_sizes, int n_in,
                              void* d_out, int out_size) {
    const float* q     = (const float*)d_in[0];
    const float* k     = (const float*)d_in[1];
    const float* v     = (const float*)d_in[2];
    const float* means = (const float*)d_in[3];
    const float* mk    = (const float*)d_in[4];
    const float* mv    = (const float*)d_in[5];
    float* out = (float*)d_out;

    cudaFuncSetAttribute(attn_kernel, cudaFuncAttributeMaxDynamicSharedMemorySize, ATTN_SMEM);

    const int nblk4 = (int)((OUT_ELEMS / 4 + 255) / 256);
    zero_kernel<<<nblk4, 256>>>(out);

    dim3 g1(TT_ / 256, BH_);
    dist_kernel<<<g1, 256>>>(q, k, means);

    select_kernel<<<BH_ * 2 * NC_, 256>>>();

    attn_kernel<<<BH_ * NC_, 256, ATTN_SMEM>>>(q, k, v, mk, mv, out);

    aux_kernel<<<1, 1>>>(out);
}